// round 15
// baseline (speedup 1.0000x reference)
#include <cuda_runtime.h>
#include <cuda_bf16.h>
#include <cstdint>

#define BB 16
#define NN 2048
#define DD 256
#define EPSF 1e-9f
#define SKIPT (-46.0f)
#define NF 6

// ---------------- scratch (static __device__ globals; no allocation) --------
__device__ __align__(256) __nv_bfloat16 g_Phi[(size_t)BB * NN * DD];
__device__ __align__(256) __nv_bfloat16 g_Lhi[(size_t)BB * NN * DD];
__device__ __align__(16) float g_pn[BB * NN];
__device__ __align__(16) float g_ln[BB * NN];
__device__ __align__(16) float g_T[BB * NN];
__device__ __align__(16) float g_W[BB * NN];
__device__ __align__(16) float g_cost[BB * NN];
__device__ __align__(16) float g_curr[BB * NN];
__device__ __align__(16) float g_bw[BB * NN];
__device__ __align__(16) float g_wrow[BB * NN];
__device__ __align__(16) int   g_minpw[BB * NN];   // float bits for atomicMin
__device__ int   g_act[NF][BB * NN];               // consumed only by rare_kernel
__device__ float g_u[BB * DD];
__device__ float g_SW[BB];
__device__ float g_SWPN[BB];

__constant__ float c_F[NF] = {-256.f, -64.f, -16.f, -4.f, -1.f, -0.25f};

// ---------------- PTX helpers (baseline <= sm_90 features only) -------------
__device__ __forceinline__ uint32_t smem_u32(const void* p) {
    uint32_t a;
    asm("{ .reg .u64 t; cvta.to.shared.u64 t, %1; cvt.u32.u64 %0, t; }" : "=r"(a) : "l"(p));
    return a;
}
__device__ __forceinline__ void cpa16(uint32_t dst, const void* src) {
    asm volatile("cp.async.cg.shared.global [%0], [%1], 16;" :: "r"(dst), "l"(src));
}
__device__ __forceinline__ void cpa_commit() {
    asm volatile("cp.async.commit_group;" ::: "memory");
}
template <int N>
__device__ __forceinline__ void cpa_wait() {
    asm volatile("cp.async.wait_group %0;" :: "n"(N) : "memory");
}

#define LDSM4(r, addr) \
    asm volatile("ldmatrix.sync.aligned.m8n8.x4.shared.b16 {%0,%1,%2,%3}, [%4];" \
                 : "=r"((r)[0]), "=r"((r)[1]), "=r"((r)[2]), "=r"((r)[3]) : "r"(addr))

#define MMA_BF16(d, a, b) \
    asm volatile("mma.sync.aligned.m16n8k16.row.col.f32.bf16.bf16.f32 " \
                 "{%0,%1,%2,%3}, {%4,%5,%6,%7}, {%8,%9}, {%0,%1,%2,%3};" \
                 : "+f"((d)[0]), "+f"((d)[1]), "+f"((d)[2]), "+f"((d)[3]) \
                 : "r"((a)[0]), "r"((a)[1]), "r"((a)[2]), "r"((a)[3]), \
                   "r"((b)[0]), "r"((b)[1]))

// ---------------- reductions ------------------------------------------------
__device__ __forceinline__ float block_reduce_256_bcast(float v) {
    __shared__ float red[8];
    __shared__ float resb;
    int lane = threadIdx.x & 31, warp = threadIdx.x >> 5;
#pragma unroll
    for (int o = 16; o; o >>= 1) v += __shfl_down_sync(0xffffffffu, v, o);
    if (lane == 0) red[warp] = v;
    __syncthreads();
    if (warp == 0) {
        v = (lane < 8) ? red[lane] : 0.f;
#pragma unroll
        for (int o = 4; o; o >>= 1) v += __shfl_down_sync(0xffffffffu, v, o);
        if (lane == 0) resb = v;
    }
    __syncthreads();
    return resb;
}

__device__ float block_reduce_1024_bcast(float v) {
    __shared__ float red[32];
    int lane = threadIdx.x & 31, warp = threadIdx.x >> 5;
#pragma unroll
    for (int o = 16; o; o >>= 1) v += __shfl_down_sync(0xffffffffu, v, o);
    if (lane == 0) red[warp] = v;
    __syncthreads();
    if (warp == 0) {
        v = red[lane];
#pragma unroll
        for (int o = 16; o; o >>= 1) v += __shfl_down_sync(0xffffffffu, v, o);
        if (lane == 0) red[0] = v;
    }
    __syncthreads();
    float r = red[0];
    __syncthreads();
    return r;
}

// ---------------- split to bf16 + row norms + FUSED init --------------------
__global__ __launch_bounds__(256) void split_norms_kernel(const float* __restrict__ P,
                                                          const float* __restrict__ L,
                                                          float* out) {
    int gtid = blockIdx.x * 256 + threadIdx.x;
    // ---- fused init (first 32K global threads) ----
    if (gtid < BB * NN) {
        g_cost[gtid] = 1.f;
        g_curr[gtid] = 1.f;
        g_T[gtid] = 0.f;
        g_W[gtid] = 0.f;
        g_minpw[gtid] = 0x7f800000;  // +inf
        if (gtid < BB * DD) g_u[gtid] = 0.f;
        if (gtid < BB) { g_SW[gtid] = 0.f; g_SWPN[gtid] = 0.f; }
        if (gtid == 0) out[0] = 0.f;
    }
    // ---- split + norms (warp per row) ----
    int warp = gtid >> 5;
    int lane = threadIdx.x & 31;
    const float* src;
    __nv_bfloat16* dhi;
    float* dn;
    int r;
    if (warp < BB * NN) { src = P; dhi = g_Phi; dn = g_pn; r = warp; }
    else { src = L; dhi = g_Lhi; dn = g_ln; r = warp - BB * NN; }
    const float4* p = (const float4*)(src + (size_t)r * DD);
    float s = 0.f;
#pragma unroll
    for (int i = 0; i < 2; ++i) {
        int idx = lane + 32 * i;
        float4 v = p[idx];
        s += v.x * v.x + v.y * v.y + v.z * v.z + v.w * v.w;
        __nv_bfloat16 h0 = __float2bfloat16(v.x), h1 = __float2bfloat16(v.y);
        __nv_bfloat16 h2 = __float2bfloat16(v.z), h3 = __float2bfloat16(v.w);
        uint2 ph;
        ph.x = ((uint32_t)__bfloat16_as_ushort(h1) << 16) | __bfloat16_as_ushort(h0);
        ph.y = ((uint32_t)__bfloat16_as_ushort(h3) << 16) | __bfloat16_as_ushort(h2);
        *(uint2*)(dhi + (size_t)r * DD + idx * 4) = ph;
    }
#pragma unroll
    for (int o = 16; o; o >>= 1) s += __shfl_down_sync(0xffffffffu, s, o);
    if (lane == 0) dn[r] = s;
}

// ---------------- bf16 min-GEMM: rowmin of pw = pn + ln - 2*(P@L^T) ---------
// Proven config: CTA 128x128, 256 thr, 8 warps of 64x32 tiles, 2 CTAs/SM,
// 3-stage cp.async pipeline. No fused tail (R13: poisons regalloc).
#define STAGE_BYTES 32768
#define ARR_BYTES 16384
#define SMEM_MM (3 * STAGE_BYTES)

__global__ __launch_bounds__(256, 2) void minpw_kernel() {
    extern __shared__ char smem[];
    uint32_t sb = smem_u32(smem);
    int tid = threadIdx.x, lane = tid & 31, wid = tid >> 5;
    int wm = wid & 1, wn = wid >> 1;
    int b = blockIdx.z;
    int row0 = blockIdx.y * 128;
    int col0 = blockIdx.x * 128;
    int bN = b * NN;

    const char* gA = (const char*)(g_Phi + ((size_t)bN + row0) * DD);
    const char* gB = (const char*)(g_Lhi + ((size_t)bN + col0) * DD);

    auto issue_loads = [&](int kc) {
        const char* srcs[2] = { gA, gB };
        uint32_t base = sb + (kc % 3) * STAGE_BYTES;
#pragma unroll
        for (int it = 0; it < 8; ++it) {
            int v = tid + 256 * it;
            int u = v & 7, r = (v >> 3) & 127, arr = v >> 10;
            uint32_t dst = base + arr * ARR_BYTES + r * 128 + ((u ^ (r & 7)) << 4);
            const char* src = srcs[arr] + (size_t)r * (DD * 2) + kc * 128 + u * 16;
            cpa16(dst, src);
        }
        cpa_commit();
    };

    float acc[4][4][4];
#pragma unroll
    for (int mi = 0; mi < 4; ++mi)
#pragma unroll
        for (int ni = 0; ni < 4; ++ni)
#pragma unroll
            for (int q = 0; q < 4; ++q) acc[mi][ni][q] = 0.f;

    int rA = lane & 15, uA = lane >> 4;
    int rB = (lane & 7) | ((lane >> 4) << 3), uB = (lane >> 3) & 1;
    uint32_t aRowOff = (uint32_t)(wm * 64 + rA) * 128;
    uint32_t bRowOff = (uint32_t)(wn * 32 + rB) * 128;
    int aMask = rA & 7, bMask = rB & 7;

    issue_loads(0);
    issue_loads(1);

#pragma unroll 1
    for (int kc = 0; kc < 4; ++kc) {
        if (kc < 2) issue_loads(kc + 2);
        if (kc == 0) cpa_wait<2>();
        else if (kc == 1) cpa_wait<2>();
        else if (kc == 2) cpa_wait<1>();
        else cpa_wait<0>();
        __syncthreads();

        uint32_t sbase = sb + (kc % 3) * STAGE_BYTES;
        uint32_t aB = sbase + aRowOff;
        uint32_t bB = sbase + ARR_BYTES + bRowOff;

#pragma unroll
        for (int ks = 0; ks < 4; ++ks) {
            uint32_t suA = (uint32_t)(((ks * 2 + uA) ^ aMask) << 4);
            uint32_t suB = (uint32_t)(((ks * 2 + uB) ^ bMask) << 4);
            uint32_t af[4][4], bf[2][4];
#pragma unroll
            for (int mi = 0; mi < 4; ++mi) LDSM4(af[mi], aB + mi * (16 * 128) + suA);
#pragma unroll
            for (int bi = 0; bi < 2; ++bi) LDSM4(bf[bi], bB + bi * (16 * 128) + suB);
#pragma unroll
            for (int mi = 0; mi < 4; ++mi)
#pragma unroll
                for (int ni = 0; ni < 4; ++ni)
                    MMA_BF16(acc[mi][ni], af[mi], &bf[ni >> 1][(ni & 1) * 2]);
        }
        __syncthreads();
    }

    // epilogue: min over row of pn + ln - 2*acc (no pw store)
    int q = lane >> 2, cq = (lane & 3) * 2;
#pragma unroll
    for (int mi = 0; mi < 4; ++mi) {
        int grow0 = row0 + wm * 64 + mi * 16 + q;
        float pn0 = g_pn[bN + grow0];
        float pn1 = g_pn[bN + grow0 + 8];
        float mn0 = 3.0e38f, mn1 = 3.0e38f;
#pragma unroll
        for (int ni = 0; ni < 4; ++ni) {
            int gc = col0 + wn * 32 + ni * 8 + cq;
            float2 lnv = *(const float2*)(g_ln + bN + gc);
            mn0 = fminf(mn0, fminf(pn0 + lnv.x - 2.f * acc[mi][ni][0],
                                   pn0 + lnv.y - 2.f * acc[mi][ni][1]));
            mn1 = fminf(mn1, fminf(pn1 + lnv.x - 2.f * acc[mi][ni][2],
                                   pn1 + lnv.y - 2.f * acc[mi][ni][3]));
        }
#pragma unroll
        for (int o = 1; o <= 2; o <<= 1) {
            mn0 = fminf(mn0, __shfl_xor_sync(0xffffffffu, mn0, o));
            mn1 = fminf(mn1, __shfl_xor_sync(0xffffffffu, mn1, o));
        }
        if ((lane & 3) == 0) {
            atomicMin(&g_minpw[bN + grow0], __float_as_int(mn0));
            atomicMin(&g_minpw[bN + grow0 + 8], __float_as_int(mn1));
        }
    }
}

// ---------------- rare path + FUSED compact (shared-memory counters) --------
__device__ void compute_pwrow(const float* __restrict__ P, const float* __restrict__ L,
                              int r, int bN, float* pwrow) {
    int lane = threadIdx.x & 31, wid = threadIdx.x >> 5;
    const float4* prow4 = (const float4*)(P + (size_t)r * DD);
    float4 pv0 = prow4[lane * 2], pv1 = prow4[lane * 2 + 1];
    float pnv = g_pn[r];
    for (int c = wid; c < NN; c += 32) {
        const float4* lrow = (const float4*)(L + ((size_t)bN + c) * DD);
        float4 l0 = lrow[lane * 2], l1 = lrow[lane * 2 + 1];
        float d = pv0.x * l0.x + pv0.y * l0.y + pv0.z * l0.z + pv0.w * l0.w +
                  pv1.x * l1.x + pv1.y * l1.y + pv1.z * l1.z + pv1.w * l1.w;
#pragma unroll
        for (int o = 16; o; o >>= 1) d += __shfl_down_sync(0xffffffffu, d, o);
        if (lane == 0) pwrow[c] = pnv + g_ln[bN + c] - 2.f * d;
    }
}

__global__ __launch_bounds__(1024) void rare_kernel(const float* __restrict__ P,
                                                    const float* __restrict__ L,
                                                    float* out) {
    __shared__ float pwrow[NN];
    __shared__ int aff[BB];
    __shared__ int s_nact[NF];
    int tid = threadIdx.x;

    // ---- fused compact: scan minpw, counters in shared, lists in global ----
    if (tid < NF) s_nact[tid] = 0;
    __syncthreads();
#pragma unroll 1
    for (int i = tid; i < BB * NN; i += 1024) {
        float minv = __int_as_float(g_minpw[i]);
#pragma unroll
        for (int j = 0; j < NF; ++j) {
            if (c_F[j] * minv >= SKIPT) {
                int p = atomicAdd(&s_nact[j], 1);
                g_act[j][p] = i;
            }
        }
    }
    __syncthreads();

    for (int j = 0; j < NF; ++j) {
        int n = s_nact[j];
        if (n == 0) continue;
        float f = c_F[j];
        if (tid < BB) aff[tid] = 0;
        __syncthreads();
        // Phase A: per active row -> S, w, accumulate T/W (cost is OLD cost)
        for (int idx = 0; idx < n; ++idx) {
            int r = g_act[j][idx];
            int b = r >> 11, bN = b * NN;
            compute_pwrow(P, L, r, bN, pwrow);
            __syncthreads();
            float s = 0.f;
            for (int c = tid; c < NN; c += 1024) s += __expf(f * pwrow[c]) * g_cost[bN + c];
            s = block_reduce_1024_bcast(s);
            float w = g_curr[r] / (s + EPSF);
            if (tid == 0) { g_wrow[r] = w; aff[b] = 1; }
            for (int c = tid; c < NN; c += 1024) {
                float bb = __expf(f * pwrow[c]) * g_cost[bN + c] * w;
                g_T[bN + c] += bb;
                g_W[bN + c] += bb * pwrow[c];
            }
            __syncthreads();
        }
        // Phase B: bw + result contribution over affected batches
        float contrib = 0.f;
        for (int b = 0; b < BB; ++b) {
            if (!aff[b]) continue;
            int bN = b * NN;
            for (int c = tid; c < NN; c += 1024) {
                float T = g_T[bN + c], W = g_W[bN + c], co = g_cost[bN + c];
                float bw = fminf(co / (T + EPSF), 1.f);
                g_bw[bN + c] = bw;
                contrib += W * bw;
            }
        }
        contrib = block_reduce_1024_bcast(contrib);
        if (tid == 0) atomicAdd(out, contrib);
        // Phase C: currency update per active row (uses OLD cost + bw)
        for (int idx = 0; idx < n; ++idx) {
            int r = g_act[j][idx];
            int b = r >> 11, bN = b * NN;
            compute_pwrow(P, L, r, bN, pwrow);
            __syncthreads();
            float u = 0.f;
            for (int c = tid; c < NN; c += 1024)
                u += __expf(f * pwrow[c]) * g_cost[bN + c] * g_bw[bN + c];
            u = block_reduce_1024_bcast(u);
            if (tid == 0) g_curr[r] = fmaxf(g_curr[r] - u * g_wrow[r], 0.f);
            __syncthreads();
        }
        // Phase D: cost update (in place, last) + zero T/W
        for (int b = 0; b < BB; ++b) {
            if (!aff[b]) continue;
            int bN = b * NN;
            for (int c = tid; c < NN; c += 1024) {
                float T = g_T[bN + c];
                g_cost[bN + c] = fmaxf(g_cost[bN + c] - T * g_bw[bN + c], 0.f);
                g_T[bN + c] = 0.f;
                g_W[bN + c] = 0.f;
            }
        }
        __syncthreads();
    }
}

// ---------------- f==0 closed form: prep (per-block costsum fused) ----------
__global__ __launch_bounds__(256) void prep_kernel(const float* __restrict__ P) {
    int b = blockIdx.y, s = blockIdx.x, t = threadIdx.x;
    int bN = b * NN;
    float cs = 0.f;
#pragma unroll
    for (int i = 0; i < 8; ++i) cs += g_cost[bN + t + 256 * i];
    cs = block_reduce_256_bcast(cs);
    float inv = 1.f / (cs + EPSF);
    int r0 = s * 16;
    float u = 0.f;
#pragma unroll
    for (int rr = 0; rr < 16; ++rr) {
        int r = bN + r0 + rr;
        u += g_curr[r] * P[(size_t)r * DD + t];
    }
    atomicAdd(&g_u[b * DD + t], u * inv);
    if (t < 16) {
        int r = bN + r0 + t;
        float w = g_curr[r];
        float wpn = w * g_pn[r];
#pragma unroll
        for (int o = 8; o; o >>= 1) {
            w += __shfl_down_sync(0x0000ffffu, w, o);
            wpn += __shfl_down_sync(0x0000ffffu, wpn, o);
        }
        if (t == 0) {
            atomicAdd(&g_SW[b], w * inv);
            atomicAdd(&g_SWPN[b], wpn * inv);
        }
    }
}

// warp per column: result += cost_c * bw_c * (SWPN + SW*ln_c - 2*<u, l_c>)
__global__ __launch_bounds__(256) void final_kernel(const float* __restrict__ L,
                                                    float* out) {
    int blk = blockIdx.x;
    int b = blk >> 8;
    int c0 = (blk & 255) * 8;
    int bN = b * NN;
    __shared__ float su[DD];
    su[threadIdx.x] = g_u[b * DD + threadIdx.x];
    __syncthreads();
    int wid = threadIdx.x >> 5, lane = threadIdx.x & 31;
    int c = c0 + wid;
    const float4* lrow = (const float4*)(L + ((size_t)bN + c) * DD);
    const float4* urow = (const float4*)su;
    float4 l0 = lrow[lane * 2], l1 = lrow[lane * 2 + 1];
    float4 u0 = urow[lane * 2], u1 = urow[lane * 2 + 1];
    float d = u0.x * l0.x + u0.y * l0.y + u0.z * l0.z + u0.w * l0.w +
              u1.x * l1.x + u1.y * l1.y + u1.z * l1.z + u1.w * l1.w;
#pragma unroll
    for (int o = 16; o; o >>= 1) d += __shfl_down_sync(0xffffffffu, d, o);
    __shared__ float rr[8];
    if (lane == 0) {
        float SW = g_SW[b], SWPN = g_SWPN[b];
        float colsum = SWPN + SW * g_ln[bN + c] - 2.f * d;
        float co = g_cost[bN + c];
        float bw = fminf(co / (co * SW + EPSF), 1.f);
        rr[wid] = co * bw * colsum;
    }
    __syncthreads();
    if (threadIdx.x == 0) {
        float t = 0.f;
#pragma unroll
        for (int i = 0; i < 8; ++i) t += rr[i];
        atomicAdd(out, t);
    }
}

// ---------------- launch ----------------------------------------------------
extern "C" void kernel_launch(void* const* d_in, const int* in_sizes, int n_in,
                              void* d_out, int out_size) {
    const float* preds = (const float*)d_in[0];
    const float* labels = (const float*)d_in[1];
    float* out = (float*)d_out;

    cudaFuncSetAttribute(minpw_kernel, cudaFuncAttributeMaxDynamicSharedMemorySize, SMEM_MM);

    split_norms_kernel<<<(2 * BB * NN) / 8, 256>>>(preds, labels, out);
    minpw_kernel<<<dim3(NN / 128, NN / 128, BB), 256, SMEM_MM>>>();
    rare_kernel<<<1, 1024>>>(preds, labels, out);
    prep_kernel<<<dim3(NN / 16, BB), 256>>>(preds);
    final_kernel<<<BB * (NN / 8), 256>>>(labels, out);
}

// round 16
// speedup vs baseline: 1.0904x; 1.0904x over previous
#include <cuda_runtime.h>
#include <cuda_bf16.h>
#include <cstdint>

#define BB 16
#define NN 2048
#define DD 256
#define EPSF 1e-9f
#define SKIPT (-46.0f)
#define NF 6

// ---------------- scratch (static __device__ globals; no allocation) --------
__device__ __align__(256) __nv_bfloat16 g_Phi[(size_t)BB * NN * DD];
__device__ __align__(256) __nv_bfloat16 g_Lhi[(size_t)BB * NN * DD];
__device__ __align__(16) float g_pn[BB * NN];
__device__ __align__(16) float g_ln[BB * NN];
__device__ __align__(16) float g_T[BB * NN];
__device__ __align__(16) float g_W[BB * NN];
__device__ __align__(16) float g_cost[BB * NN];
__device__ __align__(16) float g_curr[BB * NN];
__device__ __align__(16) float g_bw[BB * NN];
__device__ __align__(16) float g_wrow[BB * NN];
__device__ __align__(16) int   g_minpw[BB * NN];   // float bits for atomicMin
__device__ int   g_act[NF][BB * NN];
__device__ int   g_nact[NF];
__device__ float g_u[BB * DD];
__device__ float g_SW[BB];
__device__ float g_SWPN[BB];

__constant__ float c_F[NF] = {-256.f, -64.f, -16.f, -4.f, -1.f, -0.25f};

// ---------------- PTX helpers (baseline <= sm_90 features only) -------------
__device__ __forceinline__ uint32_t smem_u32(const void* p) {
    uint32_t a;
    asm("{ .reg .u64 t; cvta.to.shared.u64 t, %1; cvt.u32.u64 %0, t; }" : "=r"(a) : "l"(p));
    return a;
}
__device__ __forceinline__ void cpa16(uint32_t dst, const void* src) {
    asm volatile("cp.async.cg.shared.global [%0], [%1], 16;" :: "r"(dst), "l"(src));
}
__device__ __forceinline__ void cpa_commit() {
    asm volatile("cp.async.commit_group;" ::: "memory");
}
template <int N>
__device__ __forceinline__ void cpa_wait() {
    asm volatile("cp.async.wait_group %0;" :: "n"(N) : "memory");
}

#define LDSM4(r, addr) \
    asm volatile("ldmatrix.sync.aligned.m8n8.x4.shared.b16 {%0,%1,%2,%3}, [%4];" \
                 : "=r"((r)[0]), "=r"((r)[1]), "=r"((r)[2]), "=r"((r)[3]) : "r"(addr))

#define MMA_BF16(d, a, b) \
    asm volatile("mma.sync.aligned.m16n8k16.row.col.f32.bf16.bf16.f32 " \
                 "{%0,%1,%2,%3}, {%4,%5,%6,%7}, {%8,%9}, {%0,%1,%2,%3};" \
                 : "+f"((d)[0]), "+f"((d)[1]), "+f"((d)[2]), "+f"((d)[3]) \
                 : "r"((a)[0]), "r"((a)[1]), "r"((a)[2]), "r"((a)[3]), \
                   "r"((b)[0]), "r"((b)[1]))

// ---------------- reductions ------------------------------------------------
__device__ __forceinline__ float block_reduce_256_bcast(float v) {
    __shared__ float red[8];
    __shared__ float resb;
    int lane = threadIdx.x & 31, warp = threadIdx.x >> 5;
#pragma unroll
    for (int o = 16; o; o >>= 1) v += __shfl_down_sync(0xffffffffu, v, o);
    if (lane == 0) red[warp] = v;
    __syncthreads();
    if (warp == 0) {
        v = (lane < 8) ? red[lane] : 0.f;
#pragma unroll
        for (int o = 4; o; o >>= 1) v += __shfl_down_sync(0xffffffffu, v, o);
        if (lane == 0) resb = v;
    }
    __syncthreads();
    return resb;
}

__device__ float block_reduce_1024_bcast(float v) {
    __shared__ float red[32];
    int lane = threadIdx.x & 31, warp = threadIdx.x >> 5;
#pragma unroll
    for (int o = 16; o; o >>= 1) v += __shfl_down_sync(0xffffffffu, v, o);
    if (lane == 0) red[warp] = v;
    __syncthreads();
    if (warp == 0) {
        v = red[lane];
#pragma unroll
        for (int o = 16; o; o >>= 1) v += __shfl_down_sync(0xffffffffu, v, o);
        if (lane == 0) red[0] = v;
    }
    __syncthreads();
    float r = red[0];
    __syncthreads();
    return r;
}

// ---------------- split to bf16 + row norms + FUSED init --------------------
__global__ __launch_bounds__(256) void split_norms_kernel(const float* __restrict__ P,
                                                          const float* __restrict__ L,
                                                          float* out) {
    int gtid = blockIdx.x * 256 + threadIdx.x;
    // ---- fused init (first 32K global threads) ----
    if (gtid < BB * NN) {
        g_cost[gtid] = 1.f;
        g_curr[gtid] = 1.f;
        g_T[gtid] = 0.f;
        g_W[gtid] = 0.f;
        g_minpw[gtid] = 0x7f800000;  // +inf
        if (gtid < BB * DD) g_u[gtid] = 0.f;
        if (gtid < NF) g_nact[gtid] = 0;
        if (gtid < BB) { g_SW[gtid] = 0.f; g_SWPN[gtid] = 0.f; }
        if (gtid == 0) out[0] = 0.f;
    }
    // ---- split + norms (warp per row) ----
    int warp = gtid >> 5;
    int lane = threadIdx.x & 31;
    const float* src;
    __nv_bfloat16* dhi;
    float* dn;
    int r;
    if (warp < BB * NN) { src = P; dhi = g_Phi; dn = g_pn; r = warp; }
    else { src = L; dhi = g_Lhi; dn = g_ln; r = warp - BB * NN; }
    const float4* p = (const float4*)(src + (size_t)r * DD);
    float s = 0.f;
#pragma unroll
    for (int i = 0; i < 2; ++i) {
        int idx = lane + 32 * i;
        float4 v = p[idx];
        s += v.x * v.x + v.y * v.y + v.z * v.z + v.w * v.w;
        __nv_bfloat16 h0 = __float2bfloat16(v.x), h1 = __float2bfloat16(v.y);
        __nv_bfloat16 h2 = __float2bfloat16(v.z), h3 = __float2bfloat16(v.w);
        uint2 ph;
        ph.x = ((uint32_t)__bfloat16_as_ushort(h1) << 16) | __bfloat16_as_ushort(h0);
        ph.y = ((uint32_t)__bfloat16_as_ushort(h3) << 16) | __bfloat16_as_ushort(h2);
        *(uint2*)(dhi + (size_t)r * DD + idx * 4) = ph;
    }
#pragma unroll
    for (int o = 16; o; o >>= 1) s += __shfl_down_sync(0xffffffffu, s, o);
    if (lane == 0) dn[r] = s;
}

// ---------------- bf16 min-GEMM: rowmin of pw = pn + ln - 2*(P@L^T) ---------
// Proven config: CTA 128x128, 256 thr, 8 warps of 64x32 tiles, 2 CTAs/SM,
// 3-stage cp.async pipeline. No fused tail (R13: poisons regalloc).
#define STAGE_BYTES 32768
#define ARR_BYTES 16384
#define SMEM_MM (3 * STAGE_BYTES)

__global__ __launch_bounds__(256, 2) void minpw_kernel() {
    extern __shared__ char smem[];
    uint32_t sb = smem_u32(smem);
    int tid = threadIdx.x, lane = tid & 31, wid = tid >> 5;
    int wm = wid & 1, wn = wid >> 1;
    int b = blockIdx.z;
    int row0 = blockIdx.y * 128;
    int col0 = blockIdx.x * 128;
    int bN = b * NN;

    const char* gA = (const char*)(g_Phi + ((size_t)bN + row0) * DD);
    const char* gB = (const char*)(g_Lhi + ((size_t)bN + col0) * DD);

    auto issue_loads = [&](int kc) {
        const char* srcs[2] = { gA, gB };
        uint32_t base = sb + (kc % 3) * STAGE_BYTES;
#pragma unroll
        for (int it = 0; it < 8; ++it) {
            int v = tid + 256 * it;
            int u = v & 7, r = (v >> 3) & 127, arr = v >> 10;
            uint32_t dst = base + arr * ARR_BYTES + r * 128 + ((u ^ (r & 7)) << 4);
            const char* src = srcs[arr] + (size_t)r * (DD * 2) + kc * 128 + u * 16;
            cpa16(dst, src);
        }
        cpa_commit();
    };

    float acc[4][4][4];
#pragma unroll
    for (int mi = 0; mi < 4; ++mi)
#pragma unroll
        for (int ni = 0; ni < 4; ++ni)
#pragma unroll
            for (int q = 0; q < 4; ++q) acc[mi][ni][q] = 0.f;

    int rA = lane & 15, uA = lane >> 4;
    int rB = (lane & 7) | ((lane >> 4) << 3), uB = (lane >> 3) & 1;
    uint32_t aRowOff = (uint32_t)(wm * 64 + rA) * 128;
    uint32_t bRowOff = (uint32_t)(wn * 32 + rB) * 128;
    int aMask = rA & 7, bMask = rB & 7;

    issue_loads(0);
    issue_loads(1);

#pragma unroll 1
    for (int kc = 0; kc < 4; ++kc) {
        if (kc < 2) issue_loads(kc + 2);
        if (kc == 0) cpa_wait<2>();
        else if (kc == 1) cpa_wait<2>();
        else if (kc == 2) cpa_wait<1>();
        else cpa_wait<0>();
        __syncthreads();

        uint32_t sbase = sb + (kc % 3) * STAGE_BYTES;
        uint32_t aB = sbase + aRowOff;
        uint32_t bB = sbase + ARR_BYTES + bRowOff;

#pragma unroll
        for (int ks = 0; ks < 4; ++ks) {
            uint32_t suA = (uint32_t)(((ks * 2 + uA) ^ aMask) << 4);
            uint32_t suB = (uint32_t)(((ks * 2 + uB) ^ bMask) << 4);
            uint32_t af[4][4], bf[2][4];
#pragma unroll
            for (int mi = 0; mi < 4; ++mi) LDSM4(af[mi], aB + mi * (16 * 128) + suA);
#pragma unroll
            for (int bi = 0; bi < 2; ++bi) LDSM4(bf[bi], bB + bi * (16 * 128) + suB);
#pragma unroll
            for (int mi = 0; mi < 4; ++mi)
#pragma unroll
                for (int ni = 0; ni < 4; ++ni)
                    MMA_BF16(acc[mi][ni], af[mi], &bf[ni >> 1][(ni & 1) * 2]);
        }
        __syncthreads();
    }

    // epilogue: min over row of pn + ln - 2*acc (no pw store)
    int q = lane >> 2, cq = (lane & 3) * 2;
#pragma unroll
    for (int mi = 0; mi < 4; ++mi) {
        int grow0 = row0 + wm * 64 + mi * 16 + q;
        float pn0 = g_pn[bN + grow0];
        float pn1 = g_pn[bN + grow0 + 8];
        float mn0 = 3.0e38f, mn1 = 3.0e38f;
#pragma unroll
        for (int ni = 0; ni < 4; ++ni) {
            int gc = col0 + wn * 32 + ni * 8 + cq;
            float2 lnv = *(const float2*)(g_ln + bN + gc);
            mn0 = fminf(mn0, fminf(pn0 + lnv.x - 2.f * acc[mi][ni][0],
                                   pn0 + lnv.y - 2.f * acc[mi][ni][1]));
            mn1 = fminf(mn1, fminf(pn1 + lnv.x - 2.f * acc[mi][ni][2],
                                   pn1 + lnv.y - 2.f * acc[mi][ni][3]));
        }
#pragma unroll
        for (int o = 1; o <= 2; o <<= 1) {
            mn0 = fminf(mn0, __shfl_xor_sync(0xffffffffu, mn0, o));
            mn1 = fminf(mn1, __shfl_xor_sync(0xffffffffu, mn1, o));
        }
        if ((lane & 3) == 0) {
            atomicMin(&g_minpw[bN + grow0], __float_as_int(mn0));
            atomicMin(&g_minpw[bN + grow0 + 8], __float_as_int(mn1));
        }
    }
}

// ---------------- compact: active-row lists per negative-f iteration --------
__global__ __launch_bounds__(256) void compact_kernel() {
    int i = blockIdx.x * 256 + threadIdx.x;
    float minv = __int_as_float(g_minpw[i]);
#pragma unroll
    for (int j = 0; j < NF; ++j) {
        if (c_F[j] * minv >= SKIPT) {
            int p = atomicAdd(&g_nact[j], 1);
            g_act[j][p] = i;
        }
    }
}

// ---------------- rare path: exact auction for active rows (expected none) --
__device__ void compute_pwrow(const float* __restrict__ P, const float* __restrict__ L,
                              int r, int bN, float* pwrow) {
    int lane = threadIdx.x & 31, wid = threadIdx.x >> 5;
    const float4* prow4 = (const float4*)(P + (size_t)r * DD);
    float4 pv0 = prow4[lane * 2], pv1 = prow4[lane * 2 + 1];
    float pnv = g_pn[r];
    for (int c = wid; c < NN; c += 32) {
        const float4* lrow = (const float4*)(L + ((size_t)bN + c) * DD);
        float4 l0 = lrow[lane * 2], l1 = lrow[lane * 2 + 1];
        float d = pv0.x * l0.x + pv0.y * l0.y + pv0.z * l0.z + pv0.w * l0.w +
                  pv1.x * l1.x + pv1.y * l1.y + pv1.z * l1.z + pv1.w * l1.w;
#pragma unroll
        for (int o = 16; o; o >>= 1) d += __shfl_down_sync(0xffffffffu, d, o);
        if (lane == 0) pwrow[c] = pnv + g_ln[bN + c] - 2.f * d;
    }
}

__global__ __launch_bounds__(1024) void rare_kernel(const float* __restrict__ P,
                                                    const float* __restrict__ L,
                                                    float* out) {
    __shared__ float pwrow[NN];
    __shared__ int aff[BB];
    int tid = threadIdx.x;
    for (int j = 0; j < NF; ++j) {
        int n = g_nact[j];
        if (n == 0) continue;
        float f = c_F[j];
        if (tid < BB) aff[tid] = 0;
        __syncthreads();
        // Phase A: per active row -> S, w, accumulate T/W (cost is OLD cost)
        for (int idx = 0; idx < n; ++idx) {
            int r = g_act[j][idx];
            int b = r >> 11, bN = b * NN;
            compute_pwrow(P, L, r, bN, pwrow);
            __syncthreads();
            float s = 0.f;
            for (int c = tid; c < NN; c += 1024) s += __expf(f * pwrow[c]) * g_cost[bN + c];
            s = block_reduce_1024_bcast(s);
            float w = g_curr[r] / (s + EPSF);
            if (tid == 0) { g_wrow[r] = w; aff[b] = 1; }
            for (int c = tid; c < NN; c += 1024) {
                float bb = __expf(f * pwrow[c]) * g_cost[bN + c] * w;
                g_T[bN + c] += bb;
                g_W[bN + c] += bb * pwrow[c];
            }
            __syncthreads();
        }
        // Phase B: bw + result contribution over affected batches
        float contrib = 0.f;
        for (int b = 0; b < BB; ++b) {
            if (!aff[b]) continue;
            int bN = b * NN;
            for (int c = tid; c < NN; c += 1024) {
                float T = g_T[bN + c], W = g_W[bN + c], co = g_cost[bN + c];
                float bw = fminf(co / (T + EPSF), 1.f);
                g_bw[bN + c] = bw;
                contrib += W * bw;
            }
        }
        contrib = block_reduce_1024_bcast(contrib);
        if (tid == 0) atomicAdd(out, contrib);
        // Phase C: currency update per active row (uses OLD cost + bw)
        for (int idx = 0; idx < n; ++idx) {
            int r = g_act[j][idx];
            int b = r >> 11, bN = b * NN;
            compute_pwrow(P, L, r, bN, pwrow);
            __syncthreads();
            float u = 0.f;
            for (int c = tid; c < NN; c += 1024)
                u += __expf(f * pwrow[c]) * g_cost[bN + c] * g_bw[bN + c];
            u = block_reduce_1024_bcast(u);
            if (tid == 0) g_curr[r] = fmaxf(g_curr[r] - u * g_wrow[r], 0.f);
            __syncthreads();
        }
        // Phase D: cost update (in place, last) + zero T/W
        for (int b = 0; b < BB; ++b) {
            if (!aff[b]) continue;
            int bN = b * NN;
            for (int c = tid; c < NN; c += 1024) {
                float T = g_T[bN + c];
                g_cost[bN + c] = fmaxf(g_cost[bN + c] - T * g_bw[bN + c], 0.f);
                g_T[bN + c] = 0.f;
                g_W[bN + c] = 0.f;
            }
        }
        __syncthreads();
    }
}

// ---------------- f==0 closed form: prep (per-block costsum fused) ----------
// per (batch, 16-row chunk): u[k] += w_r * P[r][k]; SW, SWPN.
__global__ __launch_bounds__(256) void prep_kernel(const float* __restrict__ P) {
    int b = blockIdx.y, s = blockIdx.x, t = threadIdx.x;
    int bN = b * NN;
    float cs = 0.f;
#pragma unroll
    for (int i = 0; i < 8; ++i) cs += g_cost[bN + t + 256 * i];
    cs = block_reduce_256_bcast(cs);
    float inv = 1.f / (cs + EPSF);
    int r0 = s * 16;
    float u = 0.f;
#pragma unroll
    for (int rr = 0; rr < 16; ++rr) {
        int r = bN + r0 + rr;
        u += g_curr[r] * P[(size_t)r * DD + t];
    }
    atomicAdd(&g_u[b * DD + t], u * inv);
    if (t < 16) {
        int r = bN + r0 + t;
        float w = g_curr[r];
        float wpn = w * g_pn[r];
#pragma unroll
        for (int o = 8; o; o >>= 1) {
            w += __shfl_down_sync(0x0000ffffu, w, o);
            wpn += __shfl_down_sync(0x0000ffffu, wpn, o);
        }
        if (t == 0) {
            atomicAdd(&g_SW[b], w * inv);
            atomicAdd(&g_SWPN[b], wpn * inv);
        }
    }
}

// warp per column: result += cost_c * bw_c * (SWPN + SW*ln_c - 2*<u, l_c>)
__global__ __launch_bounds__(256) void final_kernel(const float* __restrict__ L,
                                                    float* out) {
    int blk = blockIdx.x;
    int b = blk >> 8;
    int c0 = (blk & 255) * 8;
    int bN = b * NN;
    __shared__ float su[DD];
    su[threadIdx.x] = g_u[b * DD + threadIdx.x];
    __syncthreads();
    int wid = threadIdx.x >> 5, lane = threadIdx.x & 31;
    int c = c0 + wid;
    const float4* lrow = (const float4*)(L + ((size_t)bN + c) * DD);
    const float4* urow = (const float4*)su;
    float4 l0 = lrow[lane * 2], l1 = lrow[lane * 2 + 1];
    float4 u0 = urow[lane * 2], u1 = urow[lane * 2 + 1];
    float d = u0.x * l0.x + u0.y * l0.y + u0.z * l0.z + u0.w * l0.w +
              u1.x * l1.x + u1.y * l1.y + u1.z * l1.z + u1.w * l1.w;
#pragma unroll
    for (int o = 16; o; o >>= 1) d += __shfl_down_sync(0xffffffffu, d, o);
    __shared__ float rr[8];
    if (lane == 0) {
        float SW = g_SW[b], SWPN = g_SWPN[b];
        float colsum = SWPN + SW * g_ln[bN + c] - 2.f * d;
        float co = g_cost[bN + c];
        float bw = fminf(co / (co * SW + EPSF), 1.f);
        rr[wid] = co * bw * colsum;
    }
    __syncthreads();
    if (threadIdx.x == 0) {
        float t = 0.f;
#pragma unroll
        for (int i = 0; i < 8; ++i) t += rr[i];
        atomicAdd(out, t);
    }
}

// ---------------- launch ----------------------------------------------------
extern "C" void kernel_launch(void* const* d_in, const int* in_sizes, int n_in,
                              void* d_out, int out_size) {
    const float* preds = (const float*)d_in[0];
    const float* labels = (const float*)d_in[1];
    float* out = (float*)d_out;

    cudaFuncSetAttribute(minpw_kernel, cudaFuncAttributeMaxDynamicSharedMemorySize, SMEM_MM);

    split_norms_kernel<<<(2 * BB * NN) / 8, 256>>>(preds, labels, out);
    minpw_kernel<<<dim3(NN / 128, NN / 128, BB), 256, SMEM_MM>>>();
    compact_kernel<<<(BB * NN) / 256, 256>>>();
    rare_kernel<<<1, 1024>>>(preds, labels, out);
    prep_kernel<<<dim3(NN / 16, BB), 256>>>(preds);
    final_kernel<<<BB * (NN / 8), 256>>>(labels, out);
}